// round 2
// baseline (speedup 1.0000x reference)
#include <cuda_runtime.h>
#include <cstdint>

// Problem constants (fixed by this problem instance)
#define Bb 64
#define Ii 2048
#define Oo 2048
#define Ss 10
#define Cc 512

// Main kernel tiling
#define TO 16              // o's per CTA
#define KC 16              // K (i) chunk
#define NC 12              // cols per (o,k) row in smem: 10 seg + 1 w + 1 pad
#define OSTR (KC*NC + 4)   // 196 floats: per-o stride in ds (bank-skewed)
#define XR 18              // xs row stride (floats): 8B-aligned rows, conflict-free
#define NCHUNK (Ii / KC)   // 128

// -------- scratch (device globals; no allocation allowed) --------
__device__ float g_ctx_mean[Bb];
__device__ float g_mean_astro[Oo];
__device__ float g_sg[Oo * Ss];
__device__ float g_effw[(size_t)Oo * Ii];

// -------- helpers --------
__device__ __forceinline__ uint32_t sa(const void* p) {
    return (uint32_t)__cvta_generic_to_shared(p);
}
__device__ __forceinline__ void cpa8(uint32_t dst, const void* src) {
    asm volatile("cp.async.ca.shared.global [%0], [%1], 8;\n" :: "r"(dst), "l"(src));
}
__device__ __forceinline__ void cpa4(uint32_t dst, const void* src) {
    asm volatile("cp.async.ca.shared.global [%0], [%1], 4;\n" :: "r"(dst), "l"(src));
}
__device__ __forceinline__ void cpa_commit() {
    asm volatile("cp.async.commit_group;\n" ::: "memory");
}
__device__ __forceinline__ void cpa_wait1() {
    asm volatile("cp.async.wait_group 1;\n" ::: "memory");
}
__device__ __forceinline__ void cpa_wait0() {
    asm volatile("cp.async.wait_group 0;\n" ::: "memory");
}
// packed fp32x2 (sm_103a FFMA2 path — 2x fp32 throughput vs FFMA 3-reg)
__device__ __forceinline__ unsigned long long pk2(float x, float y) {
    unsigned long long r;
    asm("mov.b64 %0, {%1, %2};" : "=l"(r) : "f"(x), "f"(y));
    return r;
}
__device__ __forceinline__ void ffma2(unsigned long long& d, unsigned long long a, unsigned long long b) {
    asm("fma.rn.f32x2 %0, %1, %2, %0;" : "+l"(d) : "l"(a), "l"(b));
}
__device__ __forceinline__ void unpk2(unsigned long long v, float& a, float& b) {
    asm("mov.b64 {%0, %1}, %2;" : "=f"(a), "=f"(b) : "l"(v));
}
__device__ __forceinline__ float sigmoidf_(float z) {
    return 1.0f / (1.0f + expf(-z));
}

// -------- kernel 0: per-batch context mean --------
__global__ void k_ctx(const float* __restrict__ ctx) {
    int b = blockIdx.x;                     // 64 blocks, 128 threads
    const float4* p = reinterpret_cast<const float4*>(ctx + (size_t)b * Cc);
    float4 v = p[threadIdx.x];              // 128 * 4 = 512
    float s = v.x + v.y + v.z + v.w;
    #pragma unroll
    for (int off = 16; off; off >>= 1) s += __shfl_down_sync(0xffffffffu, s, off);
    __shared__ float sm[4];
    if ((threadIdx.x & 31) == 0) sm[threadIdx.x >> 5] = s;
    __syncthreads();
    if (threadIdx.x == 0)
        g_ctx_mean[b] = (sm[0] + sm[1] + sm[2] + sm[3]) * (1.0f / Cc);
}

// -------- kernel 1: mean astrocyte modulation per o + sigmoid(gates) --------
__global__ void k_astro(const float* __restrict__ aact,
                        const float* __restrict__ athr,
                        const float* __restrict__ gates) {
    int o = blockIdx.x * blockDim.x + threadIdx.x;   // 8 x 256 = 2048
    float act = aact[o];
    float thr = athr[o];
    float s = 0.0f;
    #pragma unroll 8
    for (int b = 0; b < Bb; b++) {
        float a = sigmoidf_(g_ctx_mean[b] * act);
        s += (a > thr) ? a : 0.0f;
    }
    g_mean_astro[o] = s * (1.0f / Bb);
    #pragma unroll
    for (int j = 0; j < Ss; j++)
        g_sg[o * Ss + j] = sigmoidf_(gates[o * Ss + j]);
}

// -------- kernel 2: pruned effective weight --------
__global__ void k_effw(const float* __restrict__ weight,
                       const float* __restrict__ cstr,
                       const float* __restrict__ pthr) {
    size_t i4 = (size_t)blockIdx.x * blockDim.x + threadIdx.x;  // 4096 x 256 float4s
    float thr = pthr[0];
    float4 w = reinterpret_cast<const float4*>(weight)[i4];
    float4 c = reinterpret_cast<const float4*>(cstr)[i4];
    float4 r;
    r.x = (fabsf(w.x) * c.x > thr) ? w.x : 0.0f;
    r.y = (fabsf(w.y) * c.y > thr) ? w.y : 0.0f;
    r.z = (fabsf(w.z) * c.z > thr) ? w.z : 0.0f;
    r.w = (fabsf(w.w) * c.w > thr) ? w.w : 0.0f;
    reinterpret_cast<float4*>(g_effw)[i4] = r;
}

// -------- main fused kernel --------
// CTA: 16 o's x all 64 b. Thread (256): b0 = t&15 -> b in {b0, b0+16, b0+32, b0+48},
// oo = t>>4. Each thread: 5 f32x2 segment-pair accumulators + 1 synaptic acc per b.
__global__ void __launch_bounds__(256, 1)
k_main(const float* __restrict__ x,
       const float* __restrict__ dend,
       const float* __restrict__ bias,
       float* __restrict__ out) {
    __shared__ __align__(16) float ds[2][TO * OSTR];  // 2 x 12544 B
    __shared__ __align__(16) float xs[2][Bb * XR];    // 2 x 4608 B

    const int t = threadIdx.x;
    const int b0 = t & 15;
    const int oo = t >> 4;
    const int oo_base = blockIdx.x * TO;

    // loader mapping: one D row (o, i) per thread per chunk
    const int lk = t % KC;        // i within chunk
    const int lo = t / KC;        // o within tile
    const float* dsrc = dend + ((size_t)(oo_base + lo) * Ii + lk) * Ss;
    const float* wsrc = g_effw + (size_t)(oo_base + lo) * Ii + lk;
    // x loader: 2 ops of 8B per thread per chunk
    const int xop0_b = t >> 3, xop0_j = t & 7;            // op = t
    const int xop1_b = (t + 256) >> 3, xop1_j = t & 7;    // op = t + 256

    unsigned long long acc[4][5];
    float accw[4];
    #pragma unroll
    for (int j = 0; j < 4; j++) {
        accw[j] = 0.0f;
        #pragma unroll
        for (int p = 0; p < 5; p++) acc[j][p] = 0ull;
    }

    // ---- async chunk loader ----
    auto load_chunk = [&](int buf, int c) {
        // D segments: 5 x 8B
        const float* s = dsrc + (size_t)c * KC * Ss;
        uint32_t d = sa(&ds[buf][lo * OSTR + lk * NC]);
        #pragma unroll
        for (int j = 0; j < 5; j++) cpa8(d + j * 8, s + j * 2);
        // effective weight: 4B at col 10
        cpa4(d + 40, wsrc + (size_t)c * KC);
        // x: transpose-free rows xs[b][0..15] <- x[b][c*KC .. +15]
        const int kb = c * KC;
        cpa8(sa(&xs[buf][xop0_b * XR + xop0_j * 2]), x + (size_t)xop0_b * Ii + kb + xop0_j * 2);
        cpa8(sa(&xs[buf][xop1_b * XR + xop1_j * 2]), x + (size_t)xop1_b * Ii + kb + xop1_j * 2);
    };

    load_chunk(0, 0);
    cpa_commit();

    int buf = 0;
    for (int c = 0; c < NCHUNK; c++) {
        if (c + 1 < NCHUNK) {
            load_chunk(buf ^ 1, c + 1);
            cpa_commit();
            cpa_wait1();
        } else {
            cpa_wait0();
        }
        __syncthreads();

        const float* dbase = &ds[buf][oo * OSTR];
        const float* xbase = &xs[buf][b0 * XR];   // FIX: row base is b0*XR (was b0)
        #pragma unroll
        for (int k = 0; k < KC; k++) {
            float xv[4];
            unsigned long long xp[4];
            #pragma unroll
            for (int j = 0; j < 4; j++) {
                xv[j] = xbase[(16 * j) * XR + k];
                xp[j] = pk2(xv[j], xv[j]);
            }
            const float* dr = dbase + k * NC;
            unsigned long long dp[5];
            #pragma unroll
            for (int p = 0; p < 5; p++)
                dp[p] = *reinterpret_cast<const unsigned long long*>(dr + 2 * p);
            float wv = dr[10];
            #pragma unroll
            for (int j = 0; j < 4; j++) {
                #pragma unroll
                for (int p = 0; p < 5; p++) ffma2(acc[j][p], xp[j], dp[p]);
                accw[j] = fmaf(xv[j], wv, accw[j]);
            }
        }
        __syncthreads();
        buf ^= 1;
    }

    // ---- epilogue ----
    const int o = oo_base + oo;
    const float ma = g_mean_astro[o];
    const float bv = bias[o];
    float sg[Ss];
    #pragma unroll
    for (int s = 0; s < Ss; s++) sg[s] = g_sg[o * Ss + s];

    #pragma unroll
    for (int j = 0; j < 4; j++) {
        float v = fmaf(accw[j], ma, bv);
        #pragma unroll
        for (int p = 0; p < 5; p++) {
            float a, b;
            unpk2(acc[j][p], a, b);
            v = fmaf(sg[2 * p],     fmaxf(a, 0.0f), v);
            v = fmaf(sg[2 * p + 1], fmaxf(b, 0.0f), v);
        }
        out[(size_t)(b0 + 16 * j) * Oo + o] = fmaxf(v, 0.0f);
    }
}

extern "C" void kernel_launch(void* const* d_in, const int* in_sizes, int n_in,
                              void* d_out, int out_size) {
    const float* x      = (const float*)d_in[0];
    const float* ctx    = (const float*)d_in[1];
    // d_in[2] = prev_activation (unused by reference eval path)
    const float* weight = (const float*)d_in[3];
    const float* bias   = (const float*)d_in[4];
    const float* aact   = (const float*)d_in[5];
    const float* athr   = (const float*)d_in[6];
    const float* dend   = (const float*)d_in[7];
    const float* gates  = (const float*)d_in[8];
    const float* cstr   = (const float*)d_in[9];
    const float* pthr   = (const float*)d_in[10];
    float* out = (float*)d_out;

    k_ctx<<<Bb, 128>>>(ctx);
    k_astro<<<Oo / 256, 256>>>(aact, athr, gates);
    k_effw<<<(Oo * (Ii / 4)) / 256, 256>>>(weight, cstr, pthr);
    k_main<<<Oo / TO, 256>>>(x, dend, bias, out);
}